// round 1
// baseline (speedup 1.0000x reference)
#include <cuda_runtime.h>

#define NB   8
#define NCH  19
#define HWSZ (512*512)
#define NDIM 768
#define NCLS 1000

// scratch: inter[152] | psum[152] | cnt[152] | focal[1]
__device__ float g_scr[NB*NCH*3 + 1];

__device__ __forceinline__ float fast_exp(float x) {
    // exp(x) = 2^(x*log2e), poly on FMA pipe (no MUFU)
    float t = x * 1.4426950408889634f;
    float fz = t + 12582912.0f;                 // round-to-nearest via 1.5*2^23 magic
    int   n  = __float_as_int(fz) - 0x4B400000;
    float r  = t - (fz - 12582912.0f);          // r in [-0.5, 0.5]
    float p  = 1.3333558e-3f;
    p = fmaf(p, r, 9.6181291e-3f);
    p = fmaf(p, r, 5.5504109e-2f);
    p = fmaf(p, r, 2.4022651e-1f);
    p = fmaf(p, r, 6.9314718e-1f);
    p = fmaf(p, r, 1.0f);
    return __int_as_float(__float_as_int(p) + (n << 23));
}

__global__ void zero_scr_kernel() {
    int i = threadIdx.x;
    if (i < NB*NCH*3 + 1) g_scr[i] = 0.0f;
}

__global__ __launch_bounds__(256) void seg_kernel(const float* __restrict__ seg,
                                                  const int*   __restrict__ gt) {
    const int b = blockIdx.y;
    const float* segb = seg + (size_t)b * NCH * HWSZ;
    const int*   gtb  = gt  + (size_t)b * HWSZ;

    float psum[NCH], inter[NCH], cnt[NCH];
#pragma unroll
    for (int c = 0; c < NCH; c++) { psum[c] = 0.f; inter[c] = 0.f; cnt[c] = 0.f; }
    float focal = 0.f;

    const int tid0   = blockIdx.x * blockDim.x + threadIdx.x;
    const int stride = gridDim.x * blockDim.x;

    for (int g = tid0; g < HWSZ/4; g += stride) {
        const int px = g * 4;
        int4 t4 = *(const int4*)(gtb + px);
        float s0=0.f, s1=0.f, s2=0.f, s3=0.f;
        float eg0=0.f, eg1=0.f, eg2=0.f, eg3=0.f;
        float vg0=0.f, vg1=0.f, vg2=0.f, vg3=0.f;
#pragma unroll
        for (int c = 0; c < NCH; c++) {
            float4 p = *(const float4*)(segb + (size_t)c * HWSZ + px);
            float e0 = fast_exp(p.x), e1 = fast_exp(p.y);
            float e2 = fast_exp(p.z), e3 = fast_exp(p.w);
            s0 += e0; s1 += e1; s2 += e2; s3 += e3;
            psum[c] += (p.x + p.y) + (p.z + p.w);
            if (t4.x == c) { inter[c] += p.x; cnt[c] += 1.f; vg0 = p.x; eg0 = e0; }
            if (t4.y == c) { inter[c] += p.y; cnt[c] += 1.f; vg1 = p.y; eg1 = e1; }
            if (t4.z == c) { inter[c] += p.z; cnt[c] += 1.f; vg2 = p.z; eg2 = e2; }
            if (t4.w == c) { inter[c] += p.w; cnt[c] += 1.f; vg3 = p.w; eg3 = e3; }
        }
        // focal: alpha*(1-p_t)^2 * (lse - v_gt), lse = log(sum exp), p_t = e_gt/sum
        float ce0 = __logf(s0) - vg0, pt0 = __fdividef(eg0, s0);
        float ce1 = __logf(s1) - vg1, pt1 = __fdividef(eg1, s1);
        float ce2 = __logf(s2) - vg2, pt2 = __fdividef(eg2, s2);
        float ce3 = __logf(s3) - vg3, pt3 = __fdividef(eg3, s3);
        float o0 = 1.f - pt0, o1 = 1.f - pt1, o2 = 1.f - pt2, o3 = 1.f - pt3;
        focal += 0.25f * (o0*o0*ce0 + o1*o1*ce1 + o2*o2*ce2 + o3*o3*ce3);
    }

    // warp reduce + global atomics
    const unsigned FULL = 0xffffffffu;
    const int lane = threadIdx.x & 31;
#pragma unroll
    for (int c = 0; c < NCH; c++) {
        float a = psum[c], d = inter[c], e = cnt[c];
#pragma unroll
        for (int o = 16; o > 0; o >>= 1) {
            a += __shfl_down_sync(FULL, a, o);
            d += __shfl_down_sync(FULL, d, o);
            e += __shfl_down_sync(FULL, e, o);
        }
        if (lane == 0) {
            atomicAdd(&g_scr[b*NCH + c],                 d);   // inter
            atomicAdd(&g_scr[NB*NCH + b*NCH + c],        a);   // psum
            atomicAdd(&g_scr[2*NB*NCH + b*NCH + c],      e);   // cnt
        }
    }
    float f = focal;
#pragma unroll
    for (int o = 16; o > 0; o >>= 1) f += __shfl_down_sync(FULL, f, o);
    if (lane == 0) atomicAdd(&g_scr[3*NB*NCH], f);
}

__global__ __launch_bounds__(256) void finalize_kernel(
    const float* __restrict__ logits, const int* __restrict__ label,
    const float* __restrict__ vf, const float* __restrict__ tf,
    const float* __restrict__ mm, const int* __restrict__ ep,
    float* __restrict__ out)
{
    __shared__ float sh_vinv[8], sh_tinv[8], sh_ce[8];
    __shared__ float sh_red[8][5];
    const unsigned FULL = 0xffffffffu;
    const int tid = threadIdx.x, w = tid >> 5, lane = tid & 31;

    if (w < 8) {
        // row norms (rsqrt) for vision/text row w
        float sv = 0.f, st = 0.f;
        for (int d = lane; d < NDIM; d += 32) {
            float a = vf[w*NDIM + d]; sv = fmaf(a, a, sv);
            float b = tf[w*NDIM + d]; st = fmaf(b, b, st);
        }
#pragma unroll
        for (int o = 16; o > 0; o >>= 1) {
            sv += __shfl_down_sync(FULL, sv, o);
            st += __shfl_down_sync(FULL, st, o);
        }
        if (lane == 0) { sh_vinv[w] = rsqrtf(sv); sh_tinv[w] = rsqrtf(st); }

        // CE for row w (skip max-sub: N(0,1) logits)
        int lab = label[w];
        float s = 0.f, tv = 0.f;
        for (int c = lane; c < NCLS; c += 32) {
            float l = logits[w*NCLS + c];
            s += __expf(l);
            if (c == lab) tv = l;
        }
#pragma unroll
        for (int o = 16; o > 0; o >>= 1) {
            s  += __shfl_down_sync(FULL, s, o);
            tv += __shfl_down_sync(FULL, tv, o);
        }
        if (lane == 0) sh_ce[w] = __logf(s) - tv;
    }
    __syncthreads();

    // modal-balance accumulations
    float s_vn2 = 0.f, s_tn2 = 0.f, s_mu2v = 0.f, s_mu2t = 0.f, s_cross = 0.f;
    for (int d = tid; d < NDIM; d += 256) {
        float sumv = 0.f, sumt = 0.f;
#pragma unroll
        for (int b = 0; b < 8; b++) {
            float vn = vf[b*NDIM + d] * sh_vinv[b];
            float tn = tf[b*NDIM + d] * sh_tinv[b];
            s_vn2 = fmaf(vn, vn, s_vn2);
            s_tn2 = fmaf(tn, tn, s_tn2);
            s_cross = fmaf(vn, tn, s_cross);
            sumv += vn; sumt += tn;
        }
        s_mu2v = fmaf(sumv, sumv, s_mu2v);
        s_mu2t = fmaf(sumt, sumt, s_mu2t);
    }
#pragma unroll
    for (int o = 16; o > 0; o >>= 1) {
        s_vn2  += __shfl_down_sync(FULL, s_vn2, o);
        s_tn2  += __shfl_down_sync(FULL, s_tn2, o);
        s_mu2v += __shfl_down_sync(FULL, s_mu2v, o);
        s_mu2t += __shfl_down_sync(FULL, s_mu2t, o);
        s_cross+= __shfl_down_sync(FULL, s_cross, o);
    }
    if (lane == 0) {
        sh_red[w][0] = s_vn2; sh_red[w][1] = s_tn2;
        sh_red[w][2] = s_mu2v; sh_red[w][3] = s_mu2t; sh_red[w][4] = s_cross;
    }
    __syncthreads();

    if (tid == 0) {
        float a0=0.f,a1=0.f,a2=0.f,a3=0.f,a4=0.f;
        for (int i = 0; i < 8; i++) {
            a0 += sh_red[i][0]; a1 += sh_red[i][1]; a2 += sh_red[i][2];
            a3 += sh_red[i][3]; a4 += sh_red[i][4];
        }
        const float BD = 8.f * (float)NDIM;
        float vcons = a0 / BD - a2 / (8.f * BD);
        float tcons = a1 / BD - a3 / (8.f * BD);
        float cross = 1.f - a4 / 8.f;

        float mm0 = 0.f, mm1 = 0.f;
        for (int b = 0; b < 8; b++) { mm0 += mm[2*b]; mm1 += mm[2*b + 1]; }
        mm0 *= 0.125f; mm1 *= 0.125f;

        int e = ep ? ep[0] : 5;
        if (e < 0 || e > 1000000) e = (int)__int_as_float(e); // fp32-encoded epoch fallback
        float beta = 0.5f * powf(0.99f, (float)e);
        float mb = (1.f - beta) * vcons * mm0 + beta * tcons * mm1 + cross;

        float ce = 0.f;
        for (int b = 0; b < 8; b++) ce += sh_ce[b];
        ce *= 0.125f;

        float dsum = 0.f;
        for (int i = 0; i < NB*NCH; i++) {
            float I = g_scr[i];
            float P = g_scr[NB*NCH + i];
            float C = g_scr[2*NB*NCH + i];
            dsum += 1.f - (2.f*I + 1e-5f) / (P + C + 1e-5f);
        }
        float dice  = dsum / (float)(NB*NCH);
        float focal = g_scr[3*NB*NCH] / ((float)NB * (float)HWSZ);

        out[0] = ce + 0.3f * mb + 0.5f * (dice + focal);
    }
}

extern "C" void kernel_launch(void* const* d_in, const int* in_sizes, int n_in,
                              void* d_out, int out_size) {
    const float* logits = (const float*)d_in[0];
    const int*   label  = (const int*)  d_in[1];
    const float* vfeat  = (const float*)d_in[2];
    const float* tfeat  = (const float*)d_in[3];
    const float* mmask  = (const float*)d_in[4];
    const float* seg    = (const float*)d_in[5];
    const int*   gt     = (const int*)  d_in[6];
    const int*   ep     = (n_in >= 8) ? (const int*)d_in[7] : nullptr;

    zero_scr_kernel<<<1, 512>>>();
    seg_kernel<<<dim3(64, 8), 256>>>(seg, gt);
    finalize_kernel<<<1, 256>>>(logits, label, vfeat, tfeat, mmask, ep, (float*)d_out);
}

// round 2
// speedup vs baseline: 1.7834x; 1.7834x over previous
#include <cuda_runtime.h>

#define NB    8
#define NCH   19
#define HWSZ  (512*512)
#define NDIM  768
#define NCLS  1000
#define NSLOT 37          // grid.x: 296 CTAs = exactly 2 waves @occ1 or 1 wave @occ2

// per-block partials: [b][slot][ 0..18 inter | 19..37 psum | 38..56 cnt | 57 focal | pad ]
__device__ float g_part[NB][NSLOT][60];

__device__ __forceinline__ float fast_exp(float x) {
    // exp(x) via exp2 split; FMA-pipe only (no MUFU)
    float t = x * 1.4426950408889634f;
    float fz = t + 12582912.0f;                 // round-to-nearest magic (1.5*2^23)
    int   n  = __float_as_int(fz) - 0x4B400000;
    float r  = t - (fz - 12582912.0f);          // r in [-0.5, 0.5]
    float p  = 1.3333558e-3f;
    p = fmaf(p, r, 9.6181291e-3f);
    p = fmaf(p, r, 5.5504109e-2f);
    p = fmaf(p, r, 2.4022651e-1f);
    p = fmaf(p, r, 6.9314718e-1f);
    p = fmaf(p, r, 1.0f);
    return __int_as_float(__float_as_int(p) + (n << 23));
}

__global__ __launch_bounds__(256, 1) void seg_kernel(const float* __restrict__ seg,
                                                     const int*   __restrict__ gt) {
    const int b  = blockIdx.y;
    const int bx = blockIdx.x;
    const float* segb = seg + (size_t)b * NCH * HWSZ;
    const int*   gtb  = gt  + (size_t)b * HWSZ;

    float psum[NCH], inter[NCH], cnt[NCH];
#pragma unroll
    for (int c = 0; c < NCH; c++) { psum[c] = 0.f; inter[c] = 0.f; cnt[c] = 0.f; }
    float focal = 0.f;

    const int tid0   = bx * blockDim.x + threadIdx.x;
    const int stride = NSLOT * 256;

    for (int g = tid0; g < HWSZ/4; g += stride) {
        const int px = g * 4;
        const int4 t4 = *(const int4*)(gtb + px);
        float s0=0.f, s1=0.f, s2=0.f, s3=0.f;
        float vg0=0.f, vg1=0.f, vg2=0.f, vg3=0.f;
#pragma unroll
        for (int c = 0; c < NCH; c++) {
            float4 p = *(const float4*)(segb + (size_t)c * HWSZ + px);
            s0 += fast_exp(p.x); s1 += fast_exp(p.y);
            s2 += fast_exp(p.z); s3 += fast_exp(p.w);
            psum[c] += (p.x + p.y) + (p.z + p.w);
            // branch-free: mask arithmetic only (no BSSY/BSYNC)
            float m0 = (t4.x == c) ? 1.f : 0.f;
            float m1 = (t4.y == c) ? 1.f : 0.f;
            float m2 = (t4.z == c) ? 1.f : 0.f;
            float m3 = (t4.w == c) ? 1.f : 0.f;
            vg0 = fmaf(m0, p.x, vg0);  vg1 = fmaf(m1, p.y, vg1);
            vg2 = fmaf(m2, p.z, vg2);  vg3 = fmaf(m3, p.w, vg3);
            inter[c] = fmaf(m0, p.x, inter[c]);
            inter[c] = fmaf(m1, p.y, inter[c]);
            inter[c] = fmaf(m2, p.z, inter[c]);
            inter[c] = fmaf(m3, p.w, inter[c]);
            cnt[c] += ((m0 + m1) + (m2 + m3));
        }
        // focal: alpha*(1-p_t)^2 * (lse - v_gt); eg recomputed (cheaper than selecting)
        float eg0 = fast_exp(vg0), eg1 = fast_exp(vg1);
        float eg2 = fast_exp(vg2), eg3 = fast_exp(vg3);
        float ce0 = __logf(s0) - vg0, pt0 = __fdividef(eg0, s0);
        float ce1 = __logf(s1) - vg1, pt1 = __fdividef(eg1, s1);
        float ce2 = __logf(s2) - vg2, pt2 = __fdividef(eg2, s2);
        float ce3 = __logf(s3) - vg3, pt3 = __fdividef(eg3, s3);
        float o0 = 1.f - pt0, o1 = 1.f - pt1, o2 = 1.f - pt2, o3 = 1.f - pt3;
        focal += 0.25f * ((o0*o0*ce0 + o1*o1*ce1) + (o2*o2*ce2 + o3*o3*ce3));
    }

    // ── block reduction: warp shfl → smem → 58 partials to private slot ──
    __shared__ float sh[8][58];
    const unsigned FULL = 0xffffffffu;
    const int lane = threadIdx.x & 31;
    const int w    = threadIdx.x >> 5;
#pragma unroll
    for (int c = 0; c < NCH; c++) {
        float a = inter[c], p = psum[c], n = cnt[c];
#pragma unroll
        for (int o = 16; o > 0; o >>= 1) {
            a += __shfl_down_sync(FULL, a, o);
            p += __shfl_down_sync(FULL, p, o);
            n += __shfl_down_sync(FULL, n, o);
        }
        if (lane == 0) { sh[w][c] = a; sh[w][NCH + c] = p; sh[w][2*NCH + c] = n; }
    }
    {
        float f = focal;
#pragma unroll
        for (int o = 16; o > 0; o >>= 1) f += __shfl_down_sync(FULL, f, o);
        if (lane == 0) sh[w][57] = f;
    }
    __syncthreads();
    if (threadIdx.x < 58) {
        float a = 0.f;
#pragma unroll
        for (int i = 0; i < 8; i++) a += sh[i][threadIdx.x];
        g_part[b][bx][threadIdx.x] = a;
    }
}

__global__ __launch_bounds__(256) void finalize_kernel(
    const float* __restrict__ logits, const int* __restrict__ label,
    const float* __restrict__ vf, const float* __restrict__ tf,
    const float* __restrict__ mm, const int* __restrict__ ep,
    float* __restrict__ out)
{
    __shared__ float sh_vinv[8], sh_tinv[8], sh_ce[8];
    __shared__ float sh_red[8][5];
    __shared__ float sh_d[NB*NCH];
    __shared__ float sh_f[256];
    const unsigned FULL = 0xffffffffu;
    const int tid = threadIdx.x, w = tid >> 5, lane = tid & 31;

    // row norms + CE (one warp per batch row)
    {
        float sv = 0.f, st = 0.f;
        for (int d = lane; d < NDIM; d += 32) {
            float a = vf[w*NDIM + d]; sv = fmaf(a, a, sv);
            float b2 = tf[w*NDIM + d]; st = fmaf(b2, b2, st);
        }
#pragma unroll
        for (int o = 16; o > 0; o >>= 1) {
            sv += __shfl_down_sync(FULL, sv, o);
            st += __shfl_down_sync(FULL, st, o);
        }
        if (lane == 0) { sh_vinv[w] = rsqrtf(sv); sh_tinv[w] = rsqrtf(st); }

        int lab = label[w];
        float s = 0.f, tv = 0.f;
        for (int c = lane; c < NCLS; c += 32) {
            float l = logits[w*NCLS + c];
            s += __expf(l);
            if (c == lab) tv = l;
        }
#pragma unroll
        for (int o = 16; o > 0; o >>= 1) {
            s  += __shfl_down_sync(FULL, s, o);
            tv += __shfl_down_sync(FULL, tv, o);
        }
        if (lane == 0) sh_ce[w] = __logf(s) - tv;
    }
    __syncthreads();

    // modal-balance accumulations
    float s_vn2 = 0.f, s_tn2 = 0.f, s_mu2v = 0.f, s_mu2t = 0.f, s_cross = 0.f;
    for (int d = tid; d < NDIM; d += 256) {
        float sumv = 0.f, sumt = 0.f;
#pragma unroll
        for (int b = 0; b < 8; b++) {
            float vn = vf[b*NDIM + d] * sh_vinv[b];
            float tn = tf[b*NDIM + d] * sh_tinv[b];
            s_vn2 = fmaf(vn, vn, s_vn2);
            s_tn2 = fmaf(tn, tn, s_tn2);
            s_cross = fmaf(vn, tn, s_cross);
            sumv += vn; sumt += tn;
        }
        s_mu2v = fmaf(sumv, sumv, s_mu2v);
        s_mu2t = fmaf(sumt, sumt, s_mu2t);
    }
#pragma unroll
    for (int o = 16; o > 0; o >>= 1) {
        s_vn2  += __shfl_down_sync(FULL, s_vn2, o);
        s_tn2  += __shfl_down_sync(FULL, s_tn2, o);
        s_mu2v += __shfl_down_sync(FULL, s_mu2v, o);
        s_mu2t += __shfl_down_sync(FULL, s_mu2t, o);
        s_cross+= __shfl_down_sync(FULL, s_cross, o);
    }
    if (lane == 0) {
        sh_red[w][0] = s_vn2; sh_red[w][1] = s_tn2;
        sh_red[w][2] = s_mu2v; sh_red[w][3] = s_mu2t; sh_red[w][4] = s_cross;
    }

    // dice per-(b,c) reduce over NSLOT slots
    if (tid < NB*NCH) {
        const int b = tid / NCH, c = tid % NCH;
        float I = 0.f, P = 0.f, C = 0.f;
        for (int x = 0; x < NSLOT; x++) {
            I += g_part[b][x][c];
            P += g_part[b][x][NCH + c];
            C += g_part[b][x][2*NCH + c];
        }
        sh_d[tid] = 1.f - (2.f*I + 1e-5f) / (P + C + 1e-5f);
    }
    // focal reduce over all NB*NSLOT slots
    {
        float f = 0.f;
        for (int s = tid; s < NB*NSLOT; s += 256)
            f += g_part[s / NSLOT][s % NSLOT][57];
        sh_f[tid] = f;
    }
    __syncthreads();

    if (tid == 0) {
        float a0=0.f,a1=0.f,a2=0.f,a3=0.f,a4=0.f;
        for (int i = 0; i < 8; i++) {
            a0 += sh_red[i][0]; a1 += sh_red[i][1]; a2 += sh_red[i][2];
            a3 += sh_red[i][3]; a4 += sh_red[i][4];
        }
        const float BD = 8.f * (float)NDIM;
        float vcons = a0 / BD - a2 / (8.f * BD);
        float tcons = a1 / BD - a3 / (8.f * BD);
        float cross = 1.f - a4 / 8.f;

        float mm0 = 0.f, mm1 = 0.f;
        for (int b = 0; b < 8; b++) { mm0 += mm[2*b]; mm1 += mm[2*b + 1]; }
        mm0 *= 0.125f; mm1 *= 0.125f;

        int e = ep ? ep[0] : 5;
        float beta = 0.5f * powf(0.99f, (float)e);
        float mb = (1.f - beta) * vcons * mm0 + beta * tcons * mm1 + cross;

        float ce = 0.f;
        for (int b = 0; b < 8; b++) ce += sh_ce[b];
        ce *= 0.125f;

        float dsum = 0.f;
        for (int i = 0; i < NB*NCH; i++) dsum += sh_d[i];
        float dice = dsum / (float)(NB*NCH);

        float fsum = 0.f;
        for (int i = 0; i < 256; i++) fsum += sh_f[i];
        float focal = fsum / ((float)NB * (float)HWSZ);

        out[0] = ce + 0.3f * mb + 0.5f * (dice + focal);
    }
}

extern "C" void kernel_launch(void* const* d_in, const int* in_sizes, int n_in,
                              void* d_out, int out_size) {
    const float* logits = (const float*)d_in[0];
    const int*   label  = (const int*)  d_in[1];
    const float* vfeat  = (const float*)d_in[2];
    const float* tfeat  = (const float*)d_in[3];
    const float* mmask  = (const float*)d_in[4];
    const float* seg    = (const float*)d_in[5];
    const int*   gt     = (const int*)  d_in[6];
    const int*   ep     = (n_in >= 8) ? (const int*)d_in[7] : nullptr;

    seg_kernel<<<dim3(NSLOT, NB), 256>>>(seg, gt);
    finalize_kernel<<<1, 256>>>(logits, label, vfeat, tfeat, mmask, ep, (float*)d_out);
}

// round 3
// speedup vs baseline: 2.4923x; 1.3975x over previous
#include <cuda_runtime.h>

#define NB    8
#define NCH   19
#define HWSZ  (512*512)
#define NDIM  768
#define NCLS  1000
#define NSLOT 37          // 296 CTAs = exactly 1 wave at occ 2 (148 SMs)

// per-block partials: [b][slot][ 0..18 inter | 19..37 psum | 38..56 cnt | 57 focal | pad ]
__device__ float g_part[NB][NSLOT][60];

__device__ __forceinline__ float fast_exp(float x) {
    // exp(x) via exp2 split; degree-4 poly (rel err ~4e-5), FMA pipe only
    float t = x * 1.4426950408889634f;
    float fz = t + 12582912.0f;                 // round-to-nearest magic (1.5*2^23)
    int   n  = __float_as_int(fz) - 0x4B400000;
    float r  = t - (fz - 12582912.0f);          // r in [-0.5, 0.5]
    float p  = 9.6181291e-3f;
    p = fmaf(p, r, 5.5504109e-2f);
    p = fmaf(p, r, 2.4022651e-1f);
    p = fmaf(p, r, 6.9314718e-1f);
    p = fmaf(p, r, 1.0f);
    return __int_as_float(__float_as_int(p) + (n << 23));
}

__global__ __launch_bounds__(256, 2) void seg_kernel(const float* __restrict__ seg,
                                                     const int*   __restrict__ gt) {
    const int b  = blockIdx.y;
    const int bx = blockIdx.x;
    const float* segb = seg + (size_t)b * NCH * HWSZ;
    const int*   gtb  = gt  + (size_t)b * HWSZ;

    float psum[NCH], inter[NCH];
    int   cnti[NCH];
#pragma unroll
    for (int c = 0; c < NCH; c++) { psum[c] = 0.f; inter[c] = 0.f; cnti[c] = 0; }
    float focal = 0.f;

    const int tid0   = bx * blockDim.x + threadIdx.x;
    const int stride = NSLOT * 256;

    for (int g = tid0; g < HWSZ/4; g += stride) {
        const int px = g * 4;
        const int4 t4 = *(const int4*)(gtb + px);
        float s0=0.f, s1=0.f, s2=0.f, s3=0.f;
        float vg0=0.f, vg1=0.f, vg2=0.f, vg3=0.f;
#pragma unroll
        for (int c = 0; c < NCH; c++) {
            float4 p = *(const float4*)(segb + (size_t)c * HWSZ + px);
            s0 += fast_exp(p.x); s1 += fast_exp(p.y);
            s2 += fast_exp(p.z); s3 += fast_exp(p.w);
            psum[c] += (p.x + p.y) + (p.z + p.w);
            // branch-free masks; counts on the ALU pipe (int), values on FMA pipe
            bool b0 = (t4.x == c), b1 = (t4.y == c), b2 = (t4.z == c), b3 = (t4.w == c);
            float m0 = b0 ? 1.f : 0.f, m1 = b1 ? 1.f : 0.f;
            float m2 = b2 ? 1.f : 0.f, m3 = b3 ? 1.f : 0.f;
            vg0 = fmaf(m0, p.x, vg0);  vg1 = fmaf(m1, p.y, vg1);
            vg2 = fmaf(m2, p.z, vg2);  vg3 = fmaf(m3, p.w, vg3);
            inter[c] = fmaf(m0, p.x, inter[c]);
            inter[c] = fmaf(m1, p.y, inter[c]);
            inter[c] = fmaf(m2, p.z, inter[c]);
            inter[c] = fmaf(m3, p.w, inter[c]);
            cnti[c] += (int)b0 + (int)b1 + (int)b2 + (int)b3;
        }
        // focal: alpha*(1-p_t)^2 * (lse - v_gt); e_gt recomputed
        float eg0 = fast_exp(vg0), eg1 = fast_exp(vg1);
        float eg2 = fast_exp(vg2), eg3 = fast_exp(vg3);
        float ce0 = __logf(s0) - vg0, pt0 = __fdividef(eg0, s0);
        float ce1 = __logf(s1) - vg1, pt1 = __fdividef(eg1, s1);
        float ce2 = __logf(s2) - vg2, pt2 = __fdividef(eg2, s2);
        float ce3 = __logf(s3) - vg3, pt3 = __fdividef(eg3, s3);
        float o0 = 1.f - pt0, o1 = 1.f - pt1, o2 = 1.f - pt2, o3 = 1.f - pt3;
        focal += 0.25f * ((o0*o0*ce0 + o1*o1*ce1) + (o2*o2*ce2 + o3*o3*ce3));
    }

    // ── block reduction: warp shfl → smem → 58 partials to private slot ──
    __shared__ float sh[8][58];
    const unsigned FULL = 0xffffffffu;
    const int lane = threadIdx.x & 31;
    const int w    = threadIdx.x >> 5;
#pragma unroll
    for (int c = 0; c < NCH; c++) {
        float a = inter[c], p = psum[c], n = (float)cnti[c];
#pragma unroll
        for (int o = 16; o > 0; o >>= 1) {
            a += __shfl_down_sync(FULL, a, o);
            p += __shfl_down_sync(FULL, p, o);
            n += __shfl_down_sync(FULL, n, o);
        }
        if (lane == 0) { sh[w][c] = a; sh[w][NCH + c] = p; sh[w][2*NCH + c] = n; }
    }
    {
        float f = focal;
#pragma unroll
        for (int o = 16; o > 0; o >>= 1) f += __shfl_down_sync(FULL, f, o);
        if (lane == 0) sh[w][57] = f;
    }
    __syncthreads();
    if (threadIdx.x < 58) {
        float a = 0.f;
#pragma unroll
        for (int i = 0; i < 8; i++) a += sh[i][threadIdx.x];
        g_part[b][bx][threadIdx.x] = a;
    }
}

__global__ __launch_bounds__(256) void finalize_kernel(
    const float* __restrict__ logits, const int* __restrict__ label,
    const float* __restrict__ vf, const float* __restrict__ tf,
    const float* __restrict__ mm, const int* __restrict__ ep,
    float* __restrict__ out)
{
    __shared__ float sh_vinv[8], sh_tinv[8], sh_ce[8];
    __shared__ float sh_red[8][5];
    __shared__ float sh_blk[8];
    const unsigned FULL = 0xffffffffu;
    const int tid = threadIdx.x, w = tid >> 5, lane = tid & 31;

    // row norms + CE (one warp per batch row)
    {
        float sv = 0.f, st = 0.f;
        for (int d = lane; d < NDIM; d += 32) {
            float a  = vf[w*NDIM + d]; sv = fmaf(a, a, sv);
            float b2 = tf[w*NDIM + d]; st = fmaf(b2, b2, st);
        }
#pragma unroll
        for (int o = 16; o > 0; o >>= 1) {
            sv += __shfl_down_sync(FULL, sv, o);
            st += __shfl_down_sync(FULL, st, o);
        }
        if (lane == 0) { sh_vinv[w] = rsqrtf(sv); sh_tinv[w] = rsqrtf(st); }

        int lab = label[w];
        float s = 0.f, tv = 0.f;
        for (int c = lane; c < NCLS; c += 32) {
            float l = logits[w*NCLS + c];
            s += __expf(l);
            if (c == lab) tv = l;
        }
#pragma unroll
        for (int o = 16; o > 0; o >>= 1) {
            s  += __shfl_down_sync(FULL, s, o);
            tv += __shfl_down_sync(FULL, tv, o);
        }
        if (lane == 0) sh_ce[w] = __logf(s) - tv;
    }
    __syncthreads();

    // modal-balance accumulations
    float s_vn2 = 0.f, s_tn2 = 0.f, s_mu2v = 0.f, s_mu2t = 0.f, s_cross = 0.f;
    for (int d = tid; d < NDIM; d += 256) {
        float sumv = 0.f, sumt = 0.f;
#pragma unroll
        for (int b = 0; b < 8; b++) {
            float vn = vf[b*NDIM + d] * sh_vinv[b];
            float tn = tf[b*NDIM + d] * sh_tinv[b];
            s_vn2  = fmaf(vn, vn, s_vn2);
            s_tn2  = fmaf(tn, tn, s_tn2);
            s_cross= fmaf(vn, tn, s_cross);
            sumv += vn; sumt += tn;
        }
        s_mu2v = fmaf(sumv, sumv, s_mu2v);
        s_mu2t = fmaf(sumt, sumt, s_mu2t);
    }
#pragma unroll
    for (int o = 16; o > 0; o >>= 1) {
        s_vn2  += __shfl_down_sync(FULL, s_vn2, o);
        s_tn2  += __shfl_down_sync(FULL, s_tn2, o);
        s_mu2v += __shfl_down_sync(FULL, s_mu2v, o);
        s_mu2t += __shfl_down_sync(FULL, s_mu2t, o);
        s_cross+= __shfl_down_sync(FULL, s_cross, o);
    }
    if (lane == 0) {
        sh_red[w][0] = s_vn2;  sh_red[w][1] = s_tn2;
        sh_red[w][2] = s_mu2v; sh_red[w][3] = s_mu2t; sh_red[w][4] = s_cross;
    }

    // seg contribution per thread (dice term + focal partials), then one block reduce
    float v = 0.f;
    if (tid < NB*NCH) {
        const int b = tid / NCH, c = tid % NCH;
        float I = 0.f, P = 0.f, C = 0.f;
#pragma unroll 4
        for (int x = 0; x < NSLOT; x++) {
            I += g_part[b][x][c];
            P += g_part[b][x][NCH + c];
            C += g_part[b][x][2*NCH + c];
        }
        v = (1.f - (2.f*I + 1e-5f) / (P + C + 1e-5f)) * (0.5f / (float)(NB*NCH));
    }
    {
        float f = 0.f;
        for (int s = tid; s < NB*NSLOT; s += 256)
            f += g_part[s / NSLOT][s % NSLOT][57];
        v = fmaf(f, 0.5f / ((float)NB * (float)HWSZ), v);
    }
#pragma unroll
    for (int o = 16; o > 0; o >>= 1) v += __shfl_down_sync(FULL, v, o);
    if (lane == 0) sh_blk[w] = v;
    __syncthreads();

    if (tid == 0) {
        float segv = 0.f;
#pragma unroll
        for (int i = 0; i < 8; i++) segv += sh_blk[i];

        float a0=0.f,a1=0.f,a2=0.f,a3=0.f,a4=0.f, ce=0.f;
#pragma unroll
        for (int i = 0; i < 8; i++) {
            a0 += sh_red[i][0]; a1 += sh_red[i][1]; a2 += sh_red[i][2];
            a3 += sh_red[i][3]; a4 += sh_red[i][4]; ce += sh_ce[i];
        }
        ce *= 0.125f;
        const float BD = 8.f * (float)NDIM;
        float vcons = a0 / BD - a2 / (8.f * BD);
        float tcons = a1 / BD - a3 / (8.f * BD);
        float cross = 1.f - a4 * 0.125f;

        float mm0 = 0.f, mm1 = 0.f;
#pragma unroll
        for (int b = 0; b < 8; b++) { mm0 += mm[2*b]; mm1 += mm[2*b + 1]; }
        mm0 *= 0.125f; mm1 *= 0.125f;

        float e = (float)ep[0];
        float beta = 0.5f * __expf(e * -0.010050335853501441f);  // 0.5 * 0.99^e
        float mb = (1.f - beta) * vcons * mm0 + beta * tcons * mm1 + cross;

        out[0] = ce + 0.3f * mb + segv;
    }
}

extern "C" void kernel_launch(void* const* d_in, const int* in_sizes, int n_in,
                              void* d_out, int out_size) {
    const float* logits = (const float*)d_in[0];
    const int*   label  = (const int*)  d_in[1];
    const float* vfeat  = (const float*)d_in[2];
    const float* tfeat  = (const float*)d_in[3];
    const float* mmask  = (const float*)d_in[4];
    const float* seg    = (const float*)d_in[5];
    const int*   gt     = (const int*)  d_in[6];
    const int*   ep     = (const int*)  d_in[7];

    seg_kernel<<<dim3(NSLOT, NB), 256>>>(seg, gt);
    finalize_kernel<<<1, 256>>>(logits, label, vfeat, tfeat, mmask, ep, (float*)d_out);
}

// round 4
// speedup vs baseline: 2.5240x; 1.0127x over previous
#include <cuda_runtime.h>

#define NB    8
#define NCH   19
#define HWSZ  (512*512)
#define NDIM  768
#define NCLS  1000
#define NSLOT 36          // 288 seg CTAs + 8 misc CTAs = 296 = exactly 1 wave @occ2

// per-block partials: [b][slot][ 0..18 inter | 19..37 psum | 38..56 cnt | 57 focal | pad ]
__device__ float g_part[NB][NSLOT][60];
// misc: ce[8] | vinv[8] | tinv[8]
__device__ float g_misc[24];

__device__ __forceinline__ float fast_exp(float x) {
    // exp(x) via exp2 split; degree-4 poly (rel err ~4e-5), FMA pipe only
    float t = x * 1.4426950408889634f;
    float fz = t + 12582912.0f;                 // round-to-nearest magic (1.5*2^23)
    int   n  = __float_as_int(fz) - 0x4B400000;
    float r  = t - (fz - 12582912.0f);          // r in [-0.5, 0.5]
    float p  = 9.6181291e-3f;
    p = fmaf(p, r, 5.5504109e-2f);
    p = fmaf(p, r, 2.4022651e-1f);
    p = fmaf(p, r, 6.9314718e-1f);
    p = fmaf(p, r, 1.0f);
    return __int_as_float(__float_as_int(p) + (n << 23));
}

__global__ __launch_bounds__(256, 2) void seg_kernel(const float* __restrict__ seg,
                                                     const int*   __restrict__ gt,
                                                     const float* __restrict__ logits,
                                                     const int*   __restrict__ label,
                                                     const float* __restrict__ vf,
                                                     const float* __restrict__ tf) {
    const int b  = blockIdx.y;
    const int bx = blockIdx.x;
    const unsigned FULL = 0xffffffffu;
    const int lane = threadIdx.x & 31;
    const int w    = threadIdx.x >> 5;

    if (bx == NSLOT) {
        // ── misc CTA (one per batch row): CE + feature norms, overlapped with seg ──
        const int tid = threadIdx.x;
        float ce_p = 0.f, sv = 0.f, st = 0.f;
        if (tid < NCLS/4) {
            float4 L = ((const float4*)(logits + b*NCLS))[tid];   // 250 independent LDG.128
            ce_p = (__expf(L.x) + __expf(L.y)) + (__expf(L.z) + __expf(L.w));
        }
        if (tid < NDIM/4) {
            float4 V = ((const float4*)(vf + b*NDIM))[tid];       // 192 independent LDG.128
            sv = fmaf(V.x,V.x, fmaf(V.y,V.y, fmaf(V.z,V.z, V.w*V.w)));
            float4 T = ((const float4*)(tf + b*NDIM))[tid];
            st = fmaf(T.x,T.x, fmaf(T.y,T.y, fmaf(T.z,T.z, T.w*T.w)));
        }
#pragma unroll
        for (int o = 16; o > 0; o >>= 1) {
            ce_p += __shfl_down_sync(FULL, ce_p, o);
            sv   += __shfl_down_sync(FULL, sv, o);
            st   += __shfl_down_sync(FULL, st, o);
        }
        __shared__ float shm[8][3];
        if (lane == 0) { shm[w][0] = ce_p; shm[w][1] = sv; shm[w][2] = st; }
        __syncthreads();
        if (tid == 0) {
            float s = 0.f, a = 0.f, c = 0.f;
#pragma unroll
            for (int i = 0; i < 8; i++) { s += shm[i][0]; a += shm[i][1]; c += shm[i][2]; }
            g_misc[b]      = __logf(s) - logits[b*NCLS + label[b]];
            g_misc[8 + b]  = rsqrtf(a);
            g_misc[16 + b] = rsqrtf(c);
        }
        return;
    }

    // ── seg streaming path ──
    const float* segb = seg + (size_t)b * NCH * HWSZ;
    const int*   gtb  = gt  + (size_t)b * HWSZ;

    float psum[NCH], inter[NCH];
    int   cnti[NCH];
#pragma unroll
    for (int c = 0; c < NCH; c++) { psum[c] = 0.f; inter[c] = 0.f; cnti[c] = 0; }
    float focal = 0.f;

    const int tid0   = bx * blockDim.x + threadIdx.x;
    const int stride = NSLOT * 256;

    for (int g = tid0; g < HWSZ/4; g += stride) {
        const int px = g * 4;
        const int4 t4 = *(const int4*)(gtb + px);
        float s0=0.f, s1=0.f, s2=0.f, s3=0.f;
        float vg0=0.f, vg1=0.f, vg2=0.f, vg3=0.f;
#pragma unroll
        for (int c = 0; c < NCH; c++) {
            float4 p = *(const float4*)(segb + (size_t)c * HWSZ + px);
            s0 += fast_exp(p.x); s1 += fast_exp(p.y);
            s2 += fast_exp(p.z); s3 += fast_exp(p.w);
            psum[c] += (p.x + p.y) + (p.z + p.w);
            bool b0 = (t4.x == c), b1 = (t4.y == c), b2 = (t4.z == c), b3 = (t4.w == c);
            float m0 = b0 ? 1.f : 0.f, m1 = b1 ? 1.f : 0.f;
            float m2 = b2 ? 1.f : 0.f, m3 = b3 ? 1.f : 0.f;
            vg0 = fmaf(m0, p.x, vg0);  vg1 = fmaf(m1, p.y, vg1);
            vg2 = fmaf(m2, p.z, vg2);  vg3 = fmaf(m3, p.w, vg3);
            inter[c] = fmaf(m0, p.x, inter[c]);
            inter[c] = fmaf(m1, p.y, inter[c]);
            inter[c] = fmaf(m2, p.z, inter[c]);
            inter[c] = fmaf(m3, p.w, inter[c]);
            cnti[c] += (int)b0 + (int)b1 + (int)b2 + (int)b3;
        }
        float eg0 = fast_exp(vg0), eg1 = fast_exp(vg1);
        float eg2 = fast_exp(vg2), eg3 = fast_exp(vg3);
        float ce0 = __logf(s0) - vg0, pt0 = __fdividef(eg0, s0);
        float ce1 = __logf(s1) - vg1, pt1 = __fdividef(eg1, s1);
        float ce2 = __logf(s2) - vg2, pt2 = __fdividef(eg2, s2);
        float ce3 = __logf(s3) - vg3, pt3 = __fdividef(eg3, s3);
        float o0 = 1.f - pt0, o1 = 1.f - pt1, o2 = 1.f - pt2, o3 = 1.f - pt3;
        focal += 0.25f * ((o0*o0*ce0 + o1*o1*ce1) + (o2*o2*ce2 + o3*o3*ce3));
    }

    // block reduction: warp shfl → smem → 58 partials to private slot
    __shared__ float sh[8][58];
#pragma unroll
    for (int c = 0; c < NCH; c++) {
        float a = inter[c], p = psum[c], n = (float)cnti[c];
#pragma unroll
        for (int o = 16; o > 0; o >>= 1) {
            a += __shfl_down_sync(FULL, a, o);
            p += __shfl_down_sync(FULL, p, o);
            n += __shfl_down_sync(FULL, n, o);
        }
        if (lane == 0) { sh[w][c] = a; sh[w][NCH + c] = p; sh[w][2*NCH + c] = n; }
    }
    {
        float f = focal;
#pragma unroll
        for (int o = 16; o > 0; o >>= 1) f += __shfl_down_sync(FULL, f, o);
        if (lane == 0) sh[w][57] = f;
    }
    __syncthreads();
    if (threadIdx.x < 58) {
        float a = 0.f;
#pragma unroll
        for (int i = 0; i < 8; i++) a += sh[i][threadIdx.x];
        g_part[b][bx][threadIdx.x] = a;
    }
}

__global__ __launch_bounds__(256) void finalize_kernel(
    const float* __restrict__ vf, const float* __restrict__ tf,
    const float* __restrict__ mm, const int* __restrict__ ep,
    float* __restrict__ out)
{
    __shared__ float sh_red[8][5];
    __shared__ float sh_blk[8];
    const unsigned FULL = 0xffffffffu;
    const int tid = threadIdx.x, w = tid >> 5, lane = tid & 31;

    float vinv[8], tinv[8];
#pragma unroll
    for (int b = 0; b < 8; b++) { vinv[b] = g_misc[8 + b]; tinv[b] = g_misc[16 + b]; }

    // modal-balance accumulations (vf/tf L2-hot from misc CTAs)
    float s_vn2 = 0.f, s_tn2 = 0.f, s_mu2v = 0.f, s_mu2t = 0.f, s_cross = 0.f;
#pragma unroll
    for (int it = 0; it < NDIM/256; it++) {
        int d = it * 256 + tid;
        float sumv = 0.f, sumt = 0.f;
#pragma unroll
        for (int b = 0; b < 8; b++) {
            float vn = vf[b*NDIM + d] * vinv[b];
            float tn = tf[b*NDIM + d] * tinv[b];
            s_vn2  = fmaf(vn, vn, s_vn2);
            s_tn2  = fmaf(tn, tn, s_tn2);
            s_cross= fmaf(vn, tn, s_cross);
            sumv += vn; sumt += tn;
        }
        s_mu2v = fmaf(sumv, sumv, s_mu2v);
        s_mu2t = fmaf(sumt, sumt, s_mu2t);
    }
#pragma unroll
    for (int o = 16; o > 0; o >>= 1) {
        s_vn2  += __shfl_down_sync(FULL, s_vn2, o);
        s_tn2  += __shfl_down_sync(FULL, s_tn2, o);
        s_mu2v += __shfl_down_sync(FULL, s_mu2v, o);
        s_mu2t += __shfl_down_sync(FULL, s_mu2t, o);
        s_cross+= __shfl_down_sync(FULL, s_cross, o);
    }
    if (lane == 0) {
        sh_red[w][0] = s_vn2;  sh_red[w][1] = s_tn2;
        sh_red[w][2] = s_mu2v; sh_red[w][3] = s_mu2t; sh_red[w][4] = s_cross;
    }

    // dice term (per (b,c)) + focal partials → one block-wide value
    float v = 0.f;
    if (tid < NB*NCH) {
        const int b = tid / NCH, c = tid % NCH;
        float I = 0.f, P = 0.f, C = 0.f;
#pragma unroll
        for (int x = 0; x < NSLOT; x++) {
            I += g_part[b][x][c];
            P += g_part[b][x][NCH + c];
            C += g_part[b][x][2*NCH + c];
        }
        v = (1.f - (2.f*I + 1e-5f) / (P + C + 1e-5f)) * (0.5f / (float)(NB*NCH));
    }
    {
        float f = 0.f;
#pragma unroll
        for (int s = tid; s < NB*NSLOT; s += 256)
            f += g_part[s / NSLOT][s % NSLOT][57];
        v = fmaf(f, 0.5f / ((float)NB * (float)HWSZ), v);
    }
#pragma unroll
    for (int o = 16; o > 0; o >>= 1) v += __shfl_down_sync(FULL, v, o);
    if (lane == 0) sh_blk[w] = v;
    __syncthreads();

    if (tid == 0) {
        float segv = 0.f;
#pragma unroll
        for (int i = 0; i < 8; i++) segv += sh_blk[i];

        float a0=0.f,a1=0.f,a2=0.f,a3=0.f,a4=0.f, ce=0.f;
#pragma unroll
        for (int i = 0; i < 8; i++) {
            a0 += sh_red[i][0]; a1 += sh_red[i][1]; a2 += sh_red[i][2];
            a3 += sh_red[i][3]; a4 += sh_red[i][4]; ce += g_misc[i];
        }
        ce *= 0.125f;
        const float BD = 8.f * (float)NDIM;
        float vcons = a0 / BD - a2 / (8.f * BD);
        float tcons = a1 / BD - a3 / (8.f * BD);
        float cross = 1.f - a4 * 0.125f;

        float mm0 = 0.f, mm1 = 0.f;
#pragma unroll
        for (int b = 0; b < 8; b++) { mm0 += mm[2*b]; mm1 += mm[2*b + 1]; }
        mm0 *= 0.125f; mm1 *= 0.125f;

        float e = (float)ep[0];
        float beta = 0.5f * __expf(e * -0.010050335853501441f);  // 0.5 * 0.99^e
        float mb = (1.f - beta) * vcons * mm0 + beta * tcons * mm1 + cross;

        out[0] = ce + 0.3f * mb + segv;
    }
}

extern "C" void kernel_launch(void* const* d_in, const int* in_sizes, int n_in,
                              void* d_out, int out_size) {
    const float* logits = (const float*)d_in[0];
    const int*   label  = (const int*)  d_in[1];
    const float* vfeat  = (const float*)d_in[2];
    const float* tfeat  = (const float*)d_in[3];
    const float* mmask  = (const float*)d_in[4];
    const float* seg    = (const float*)d_in[5];
    const int*   gt     = (const int*)  d_in[6];
    const int*   ep     = (const int*)  d_in[7];

    seg_kernel<<<dim3(NSLOT + 1, NB), 256>>>(seg, gt, logits, label, vfeat, tfeat);
    finalize_kernel<<<1, 256>>>(vfeat, tfeat, mmask, ep, (float*)d_out);
}